// round 1
// baseline (speedup 1.0000x reference)
#include <cuda_runtime.h>
#include <cuda_bf16.h>

#define B_  4096
#define S_  200
#define D_  64
#define NT  256

// -------- shared memory layout (floats) --------
#define OFF_EMB   0                    // 200*65 = 13000  (row-padded embeddings)
#define OFF_SATT  (OFF_EMB + 13000)    // 200*5  = 1000   (att scores, later exp values)
#define OFF_AW    (OFF_SATT + 1000)    // 320             (att_w [5][64])
#define OFF_AB    (OFF_AW + 320)       // 8               (att_b)
#define OFF_WC    (OFF_AB + 8)         // 18*64 = 1152    (W0..W4 concatenated)
#define OFF_ROWS  (OFF_WC + 1152)      // 200 (ints)      (gather indices)
#define OFF_PART  (OFF_ROWS + 200)     // 4*5*64 = 1280   (partial user_rep)
#define OFF_UREP  (OFF_PART + 1280)    // 5*65 = 325 -> 328
#define OFF_SINV  (OFF_UREP + 328)     // 8               (1/softmax_sum per k)
#define OFF_Z     (OFF_SINV + 8)       // 20              (18 logits)
#define OFF_LG    (OFF_Z + 20)         // 8               (per-group loss)
#define SMEM_FLOATS (OFF_LG + 8)       // 17324 floats = 69296 bytes

__device__ float g_loss[B_];           // per-batch loss partials (deterministic 2-stage reduce)

__global__ void __launch_bounds__(NT)
tan_kernel(const int* __restrict__ x, const float* __restrict__ y,
           const float* __restrict__ emb_table,
           const float* __restrict__ att_w, const float* __restrict__ att_b,
           const float* __restrict__ W0, const float* __restrict__ W1,
           const float* __restrict__ W2, const float* __restrict__ W3,
           const float* __restrict__ W4,
           float* __restrict__ out)
{
    extern __shared__ float sm[];
    float* emb  = sm + OFF_EMB;
    float* satt = sm + OFF_SATT;
    float* aw   = sm + OFF_AW;
    float* ab   = sm + OFF_AB;
    float* Wc   = sm + OFF_WC;
    int*   rows = (int*)(sm + OFF_ROWS);
    float* part = sm + OFF_PART;
    float* urep = sm + OFF_UREP;
    float* sinv = sm + OFF_SINV;
    float* zb   = sm + OFF_Z;
    float* lg   = sm + OFF_LG;

    const int tid = threadIdx.x;
    const int b   = blockIdx.x;

    // ---- Phase A: stage small weights + gather indices into SMEM ----
    for (int i = tid; i < 320; i += NT) aw[i] = att_w[i];
    if (tid < 5) ab[tid] = att_b[tid];
    for (int i = tid; i < 128; i += NT) Wc[i]       = W0[i];
    for (int i = tid; i < 256; i += NT) Wc[128 + i] = W1[i];
    for (int i = tid; i < 256; i += NT) Wc[384 + i] = W2[i];
    for (int i = tid; i < 128; i += NT) Wc[640 + i] = W3[i];
    for (int i = tid; i < 384; i += NT) Wc[768 + i] = W4[i];
    for (int s = tid; s < S_; s += NT)  rows[s] = x[b * S_ + s];
    __syncthreads();

    // ---- Phase B: gather 200 embedding rows (float4, 16 threads/row) ----
    for (int idx = tid; idx < S_ * 16; idx += NT) {
        const int s = idx >> 4, q = idx & 15;
        const float4 v = __ldg((const float4*)(emb_table + (long)rows[s] * D_ + q * 4));
        float* p = emb + s * 65 + q * 4;
        p[0] = v.x; p[1] = v.y; p[2] = v.z; p[3] = v.w;
    }
    __syncthreads();

    // ---- Phase C: attention logits, tanh (one thread per s) ----
    if (tid < S_) {
        const float* e = emb + tid * 65;
        float a0 = ab[0], a1 = ab[1], a2 = ab[2], a3 = ab[3], a4 = ab[4];
#pragma unroll
        for (int i = 0; i < 64; i++) {
            const float ev = e[i];
            a0 += ev * aw[i];
            a1 += ev * aw[64 + i];
            a2 += ev * aw[128 + i];
            a3 += ev * aw[192 + i];
            a4 += ev * aw[256 + i];
        }
        float* sa = satt + tid * 5;
        sa[0] = tanhf(a0); sa[1] = tanhf(a1); sa[2] = tanhf(a2);
        sa[3] = tanhf(a3); sa[4] = tanhf(a4);
    }
    __syncthreads();

    // ---- Phase D: softmax over S per attention head k (one warp per k) ----
    const int warp = tid >> 5, lane = tid & 31;
    if (warp < 5) {
        const int k = warp;
        float m = -1e30f;
        for (int s = lane; s < S_; s += 32) m = fmaxf(m, satt[s * 5 + k]);
#pragma unroll
        for (int o = 16; o; o >>= 1) m = fmaxf(m, __shfl_xor_sync(0xffffffffu, m, o));
        float sum = 0.f;
        for (int s = lane; s < S_; s += 32) {
            const float e = __expf(satt[s * 5 + k] - m);
            satt[s * 5 + k] = e;                 // keep unnormalized; fold 1/sum later
            sum += e;
        }
#pragma unroll
        for (int o = 16; o; o >>= 1) sum += __shfl_xor_sync(0xffffffffu, sum, o);
        if (lane == 0) sinv[k] = 1.0f / sum;
    }
    __syncthreads();

    // ---- Phase E: user_rep[k][d] = sum_s emb[s][d] * score[s][k] ----
    // 4 groups of 64 threads, each handles 50 s-values -> each emb row read once.
    {
        const int g = tid >> 6, d = tid & 63;
        float a0 = 0, a1 = 0, a2 = 0, a3 = 0, a4 = 0;
        const int s0 = g * 50;
        for (int s = s0; s < s0 + 50; ++s) {
            const float e = emb[s * 65 + d];
            const float* sa = satt + s * 5;
            a0 += e * sa[0]; a1 += e * sa[1]; a2 += e * sa[2];
            a3 += e * sa[3]; a4 += e * sa[4];
        }
        float* pp = part + g * 320 + d;
        pp[0] = a0; pp[64] = a1; pp[128] = a2; pp[192] = a3; pp[256] = a4;
    }
    __syncthreads();
    for (int j = tid; j < 320; j += NT) {
        const int k = j >> 6, d = j & 63;
        const float v = part[k * 64 + d] + part[320 + k * 64 + d] +
                        part[640 + k * 64 + d] + part[960 + k * 64 + d];
        urep[k * 65 + d] = v * sinv[k];
    }
    __syncthreads();

    // ---- Phase F: 18 logits, per-group softmax + loss ----
    if (tid < 18) {
        const int j = tid;
        const int g = (j < 2) ? 0 : (j < 6) ? 1 : (j < 10) ? 2 : (j < 12) ? 3 : 4;
        const float* w = Wc + j * 64;
        const float* u = urep + g * 65;
        float z = 0.f;
#pragma unroll
        for (int i = 0; i < 64; i++) z += u[i] * w[i];
        zb[j] = z;
    }
    __syncthreads();
    if (tid < 5) {
        const int cum[6] = {0, 2, 6, 10, 12, 18};
        const int g = tid, c0 = cum[g], n = cum[g + 1] - c0;
        float m = -1e30f;
        for (int j = 0; j < n; j++) m = fmaxf(m, zb[c0 + j]);
        float sum = 0.f;
        for (int j = 0; j < n; j++) sum += __expf(zb[c0 + j] - m);
        const float inv = 1.0f / sum;
        const float lse = m + __logf(sum);
        float lo = 0.f;
        for (int j = 0; j < n; j++) {
            const float zv = zb[c0 + j];
            out[b * 18 + c0 + j] = __expf(zv - m) * inv;
            lo -= y[b * 18 + c0 + j] * (zv - lse);   // y is one-hot
        }
        lg[g] = lo;
    }
    __syncthreads();
    if (tid == 0) g_loss[b] = lg[0] + lg[1] + lg[2] + lg[3] + lg[4];
}

// Deterministic final loss reduction (fixed tree -> bit-identical every replay).
__global__ void loss_reduce(float* __restrict__ out)
{
    __shared__ float sh[256];
    const int tid = threadIdx.x;
    float s = 0.f;
    for (int i = tid; i < B_; i += 256) s += g_loss[i];
    sh[tid] = s;
    __syncthreads();
    for (int o = 128; o; o >>= 1) {
        if (tid < o) sh[tid] += sh[tid + o];
        __syncthreads();
    }
    if (tid == 0) out[B_ * 18] = sh[0] * (1.0f / B_);
}

extern "C" void kernel_launch(void* const* d_in, const int* in_sizes, int n_in,
                              void* d_out, int out_size)
{
    const int*   x   = (const int*)  d_in[0];
    const float* y   = (const float*)d_in[1];
    const float* emb = (const float*)d_in[2];
    const float* aw  = (const float*)d_in[3];
    const float* ab  = (const float*)d_in[4];
    const float* W0  = (const float*)d_in[5];
    const float* W1  = (const float*)d_in[6];
    const float* W2  = (const float*)d_in[7];
    const float* W3  = (const float*)d_in[8];
    const float* W4  = (const float*)d_in[9];
    float* out = (float*)d_out;

    const size_t smem = SMEM_FLOATS * sizeof(float);
    cudaFuncSetAttribute(tan_kernel, cudaFuncAttributeMaxDynamicSharedMemorySize, (int)smem);
    tan_kernel<<<B_, NT, smem>>>(x, y, emb, aw, ab, W0, W1, W2, W3, W4, out);
    loss_reduce<<<1, 256>>>(out);
}